// round 5
// baseline (speedup 1.0000x reference)
#include <cuda_runtime.h>
#include <cuda_bf16.h>
#include <cstdint>

// GRU encoder B=512 T=128 E=H=512 L=2 — warp-MMA (HMMA bf16) hi/lo 3-pass pipeline.
// R5: GEMM retiled for occupancy — CTA 64x128, 8 warps, 96KB smem, 2 CTAs/SM
// (288 CTAs, all resident), fixing the latency-bound profile of R4.

namespace {

constexpr int B_ = 512, T_ = 128, H_ = 512, L_ = 2;
constexpr int NG = 1536;                  // 3*H
constexpr size_t BH  = (size_t)B_ * H_;
constexpr size_t BNG = (size_t)B_ * NG;
constexpr size_t WSZ = (size_t)NG * 512;  // one weight matrix
constexpr int MT = 64, NT = 128, KC = 64;
constexpr int NITER = 512 / KC;           // 8

// smem stage layout: Ahi | Alo | Bhi | Blo   (rows of 64 bf16 = 128B, SW128)
constexpr int AH_OFF = 0;
constexpr int AL_OFF = MT * 128;              //  8192
constexpr int BH_OFF = 2 * MT * 128;          // 16384
constexpr int BL_OFF = BH_OFF + NT * 128;     // 32768
constexpr int STAGE_BYTES = BL_OFF + NT * 128; // 49152
constexpr int SMEM_ALLOC = 2 * STAGE_BYTES;    // 98304 per CTA -> 2 CTAs/SM

__device__ __align__(256) float g_scr[3 * BNG];          // gh0 | gi1 | gh1
__device__ __align__(256) float g_P[128 * NG];           // emb @ Wi0^T (exact fp32)
__device__ __align__(256) __nv_bfloat16 g_Whi[3 * WSZ];  // Wh0 | Wi1 | Wh1 (hi)
__device__ __align__(256) __nv_bfloat16 g_Wlo[3 * WSZ];
__device__ __align__(256) __nv_bfloat16 g_Ahi[2 * BH];   // per-layer hidden (hi)
__device__ __align__(256) __nv_bfloat16 g_Alo[2 * BH];

__device__ __forceinline__ uint32_t s2u(const void* p) {
    uint32_t a;
    asm("{ .reg .u64 t; cvta.to.shared.u64 t, %1; cvt.u32.u64 %0, t; }" : "=r"(a) : "l"(p));
    return a;
}
__device__ __forceinline__ uint32_t sw128(uint32_t b) { return b ^ ((b >> 3) & 0x70); }
__device__ __forceinline__ void cp16(uint32_t dst, const void* src) {
    asm volatile("cp.async.cg.shared.global [%0], [%1], 16;" :: "r"(dst), "l"(src));
}
__device__ __forceinline__ void ldsm4(uint32_t* r, uint32_t addr) {
    asm volatile("ldmatrix.sync.aligned.m8n8.x4.shared.b16 {%0,%1,%2,%3}, [%4];"
                 : "=r"(r[0]), "=r"(r[1]), "=r"(r[2]), "=r"(r[3]) : "r"(addr));
}
__device__ __forceinline__ void mma16816(float* c, const uint32_t* a, const uint32_t* b) {
    asm volatile(
        "mma.sync.aligned.m16n8k16.row.col.f32.bf16.bf16.f32 "
        "{%0,%1,%2,%3}, {%4,%5,%6,%7}, {%8,%9}, {%0,%1,%2,%3};"
        : "+f"(c[0]), "+f"(c[1]), "+f"(c[2]), "+f"(c[3])
        : "r"(a[0]), "r"(a[1]), "r"(a[2]), "r"(a[3]), "r"(b[0]), "r"(b[1]));
}

// ============================ GEMM ============================
// job0: gh0 = h0(t-1) @ Wh0^T | job1: gi1 = h0(t-1) @ Wi1^T | job2: gh1 = h1(t-2) @ Wh1^T
__global__ void __launch_bounds__(256, 2) gemm_step(int t) {
    const int job = blockIdx.z;
    if (job == 0) { if (t >= T_) return; } else { if (t < 1) return; }

    const int a_sel = (job == 2) ? 1 : 0;
    const __nv_bfloat16* __restrict__ Ahi = g_Ahi + (size_t)a_sel * BH;
    const __nv_bfloat16* __restrict__ Alo = g_Alo + (size_t)a_sel * BH;
    const __nv_bfloat16* __restrict__ Bhi = g_Whi + (size_t)job * WSZ;
    const __nv_bfloat16* __restrict__ Blo = g_Wlo + (size_t)job * WSZ;
    float* __restrict__ dst = g_scr + (size_t)job * BNG;

    const int m0 = blockIdx.y * MT, n0 = blockIdx.x * NT;
    const int tid = threadIdx.x, wid = tid >> 5, lane = tid & 31;
    const int warp_m = wid & 3, warp_n = wid >> 2;   // 4M x 2N, warp tile 16x64

    extern __shared__ char smraw[];
    const uint32_t smb = s2u(smraw);

    auto load_stage = [&](int s, int k0) {
        const uint32_t st = smb + s * STAGE_BYTES;
        #pragma unroll
        for (int i = 0; i < 2; i++) {                 // A hi/lo: 64 rows x 8 chunks
            int c = tid + i * 256;
            int row = c >> 3, col = c & 7;
            uint32_t off = sw128((uint32_t)(row * 128 + col * 16));
            size_t ga = (size_t)(m0 + row) * 512 + k0 + col * 8;
            cp16(st + AH_OFF + off, Ahi + ga);
            cp16(st + AL_OFF + off, Alo + ga);
        }
        #pragma unroll
        for (int i = 0; i < 4; i++) {                 // B hi/lo: 128 rows x 8 chunks
            int c = tid + i * 256;
            int row = c >> 3, col = c & 7;
            uint32_t off = sw128((uint32_t)(row * 128 + col * 16));
            size_t gb = (size_t)(n0 + row) * 512 + k0 + col * 8;
            cp16(st + BH_OFF + off, Bhi + gb);
            cp16(st + BL_OFF + off, Blo + gb);
        }
        asm volatile("cp.async.commit_group;");
    };

    load_stage(0, 0);
    load_stage(1, KC);

    // ldmatrix lane selectors (identical layout math to R4, warp tile 16x64)
    const int aRow  = warp_m * 16 + (lane & 15);
    const int aKsel = ((lane >> 4) & 1) * 16;                     // bytes
    const int bRow  = warp_n * 64 + ((lane >> 4) & 1) * 8 + (lane & 7);
    const int bKsel = ((lane >> 3) & 1) * 16;                     // bytes

    float acc[8][4];
    #pragma unroll
    for (int ni = 0; ni < 8; ni++)
        #pragma unroll
        for (int q = 0; q < 4; q++) acc[ni][q] = 0.0f;

    for (int j = 0; j < NITER; j++) {
        if (j < NITER - 1) asm volatile("cp.async.wait_group 1;");
        else               asm volatile("cp.async.wait_group 0;");
        __syncthreads();
        const uint32_t st = smb + (j & 1) * STAGE_BYTES;

        #pragma unroll
        for (int ks = 0; ks < KC / 16; ks++) {
            uint32_t ah[4], al[4], bh[4][4], bl[4][4];
            {
                uint32_t off = sw128((uint32_t)(aRow * 128 + ks * 32 + aKsel));
                ldsm4(ah, st + AH_OFF + off);
                ldsm4(al, st + AL_OFF + off);
            }
            #pragma unroll
            for (int g = 0; g < 4; g++) {
                uint32_t off = sw128((uint32_t)((bRow + g * 16) * 128 + ks * 32 + bKsel));
                ldsm4(bh[g], st + BH_OFF + off);
                ldsm4(bl[g], st + BL_OFF + off);
            }
            #pragma unroll
            for (int ni = 0; ni < 8; ni++) {
                const uint32_t* bhp = &bh[ni >> 1][(ni & 1) * 2];
                const uint32_t* blp = &bl[ni >> 1][(ni & 1) * 2];
                mma16816(acc[ni], ah, bhp);
                mma16816(acc[ni], ah, blp);
                mma16816(acc[ni], al, bhp);
            }
        }
        if (j + 2 < NITER) {
            __syncthreads();                 // all warps done reading this buffer
            load_stage(j & 1, (j + 2) * KC);
        }
    }

    // epilogue: fragment scatter to fp32 scratch
    const int row = m0 + warp_m * 16 + (lane >> 2);
    #pragma unroll
    for (int ni = 0; ni < 8; ni++) {
        int col = n0 + warp_n * 64 + ni * 8 + (lane & 3) * 2;
        *(float2*)(dst + (size_t)row * NG + col) = make_float2(acc[ni][0], acc[ni][1]);
        *(float2*)(dst + (size_t)(row + 8) * NG + col) = make_float2(acc[ni][2], acc[ni][3]);
    }
}

// ============================ gates ============================
__global__ void __launch_bounds__(256) gate_step(
        float* __restrict__ out, const int* __restrict__ input,
        const float* __restrict__ h0init,
        const float* __restrict__ b_ih, const float* __restrict__ b_hh,
        int t, int write_final) {
    const int layer = blockIdx.y;
    const int s = (layer == 0) ? t : t - 1;
    if (s < 0 || s >= T_) return;

    const int e4 = blockIdx.x * 256 + threadIdx.x;   // 65536 float4 per layer
    const int b = e4 >> 7;
    const int h = (e4 & 127) * 4;

    float4 gi_r, gi_z, gi_n;
    if (layer == 0) {
        const float* P = g_P + (size_t)input[b * T_ + s] * NG;
        gi_r = *(const float4*)(P + h);
        gi_z = *(const float4*)(P + 512 + h);
        gi_n = *(const float4*)(P + 1024 + h);
    } else {
        const float* G = g_scr + BNG + (size_t)b * NG;   // gi1
        gi_r = *(const float4*)(G + h);
        gi_z = *(const float4*)(G + 512 + h);
        gi_n = *(const float4*)(G + 1024 + h);
    }
    const float* GH = g_scr + (layer == 0 ? (size_t)0 : 2 * BNG) + (size_t)b * NG;
    float4 gh_r = *(const float4*)(GH + h);
    float4 gh_z = *(const float4*)(GH + 512 + h);
    float4 gh_n = *(const float4*)(GH + 1024 + h);

    const float* hp_ptr = (s == 0) ? (h0init + (size_t)layer * BH)
                                   : (out + (size_t)((s - 1) * L_ + layer) * BH);
    float4 hp = *(const float4*)(hp_ptr + (size_t)b * H_ + h);

    const float* bi = b_ih + layer * NG;
    const float* bh = b_hh + layer * NG;
    float4 bir = *(const float4*)(bi + h), biz = *(const float4*)(bi + 512 + h),
           bin = *(const float4*)(bi + 1024 + h);
    float4 bhr = *(const float4*)(bh + h), bhz = *(const float4*)(bh + 512 + h),
           bhn = *(const float4*)(bh + 1024 + h);

    float hv[4];
    #pragma unroll
    for (int i = 0; i < 4; i++) {
        float r = 1.0f / (1.0f + expf(-((&gi_r.x)[i] + (&bir.x)[i] + (&gh_r.x)[i] + (&bhr.x)[i])));
        float z = 1.0f / (1.0f + expf(-((&gi_z.x)[i] + (&biz.x)[i] + (&gh_z.x)[i] + (&bhz.x)[i])));
        float n = tanhf((&gi_n.x)[i] + (&bin.x)[i] + r * ((&gh_n.x)[i] + (&bhn.x)[i]));
        hv[i] = (1.0f - z) * n + z * (&hp.x)[i];
    }

    const size_t eoff = (size_t)b * H_ + h;
    *(float4*)(out + (size_t)(s * L_ + layer) * BH + eoff) =
        make_float4(hv[0], hv[1], hv[2], hv[3]);

    __nv_bfloat16* ah = g_Ahi + (size_t)layer * BH + eoff;
    __nv_bfloat16* al = g_Alo + (size_t)layer * BH + eoff;
    #pragma unroll
    for (int i = 0; i < 4; i++) {
        __nv_bfloat16 hi = __float2bfloat16(hv[i]);
        ah[i] = hi;
        al[i] = __float2bfloat16(hv[i] - __bfloat162float(hi));
    }

    if (write_final && s == T_ - 1)
        *(float4*)(out + (size_t)T_ * L_ * BH + (size_t)layer * BH + eoff) =
            make_float4(hv[0], hv[1], hv[2], hv[3]);
}

// ============================ prep ============================
__global__ void __launch_bounds__(256) prep_P(const float* __restrict__ emb,
                                              const float* __restrict__ w_ih) {
    // grid (NG/64, 128/32): P[v][n] = sum_k emb[v][k] * Wi0[n][k]  (exact fp32)
    const int n = blockIdx.x * 64 + (threadIdx.x & 63);
    const int vl = (threadIdx.x >> 6) * 8;
    __shared__ float es[64][33];
    float acc[8] = {};
    for (int k0 = 0; k0 < 512; k0 += 64) {
        __syncthreads();
        #pragma unroll
        for (int i = 0; i < 2; i++) {
            int lin = threadIdx.x + i * 256;
            int vv = lin >> 4, k4 = lin & 15;
            float4 e = *(const float4*)(emb + (size_t)(blockIdx.y * 32 + vv) * 512 + k0 + k4 * 4);
            es[k4 * 4 + 0][vv] = e.x; es[k4 * 4 + 1][vv] = e.y;
            es[k4 * 4 + 2][vv] = e.z; es[k4 * 4 + 3][vv] = e.w;
        }
        __syncthreads();
        const float* wp = w_ih + (size_t)n * 512 + k0;
        #pragma unroll 16
        for (int kk = 0; kk < 64; kk++) {
            float wv = wp[kk];
            #pragma unroll
            for (int j = 0; j < 8; j++) acc[j] = fmaf(wv, es[kk][vl + j], acc[j]);
        }
    }
    for (int j = 0; j < 8; j++)
        g_P[(size_t)(blockIdx.y * 32 + vl + j) * NG + n] = acc[j];
}

__global__ void __launch_bounds__(256) prep_W(const float* __restrict__ w_ih,
                                              const float* __restrict__ w_hh) {
    size_t e4 = ((size_t)blockIdx.x * 256 + threadIdx.x) * 4;   // over 3*WSZ
    size_t job = e4 / WSZ, off = e4 % WSZ;
    const float* src = (job == 0) ? (w_hh + off)
                     : (job == 1) ? (w_ih + WSZ + off) : (w_hh + WSZ + off);
    float4 v = *(const float4*)src;
    union { __nv_bfloat16 b[4]; uint2 u; } hi, lo;
    float f[4] = {v.x, v.y, v.z, v.w};
    #pragma unroll
    for (int i = 0; i < 4; i++) {
        hi.b[i] = __float2bfloat16(f[i]);
        lo.b[i] = __float2bfloat16(f[i] - __bfloat162float(hi.b[i]));
    }
    *(uint2*)(g_Whi + e4) = hi.u;
    *(uint2*)(g_Wlo + e4) = lo.u;
}

__global__ void __launch_bounds__(256) prep_A(const float* __restrict__ h0) {
    size_t e4 = ((size_t)blockIdx.x * 256 + threadIdx.x) * 4;   // over 2*BH
    float4 v = *(const float4*)(h0 + e4);
    union { __nv_bfloat16 b[4]; uint2 u; } hi, lo;
    float f[4] = {v.x, v.y, v.z, v.w};
    #pragma unroll
    for (int i = 0; i < 4; i++) {
        hi.b[i] = __float2bfloat16(f[i]);
        lo.b[i] = __float2bfloat16(f[i] - __bfloat162float(hi.b[i]));
    }
    *(uint2*)(g_Ahi + e4) = hi.u;
    *(uint2*)(g_Alo + e4) = lo.u;
}

} // namespace

extern "C" void kernel_launch(void* const* d_in, const int* in_sizes, int n_in,
                              void* d_out, int out_size) {
    const int*   input = (const int*)  d_in[0];
    const float* h0    = (const float*)d_in[1];
    const float* emb   = (const float*)d_in[2];
    const float* w_ih  = (const float*)d_in[3];
    const float* w_hh  = (const float*)d_in[4];
    const float* b_ih  = (const float*)d_in[5];
    const float* b_hh  = (const float*)d_in[6];
    float* out = (float*)d_out;

    const long long states_elems = (long long)T_ * L_ * B_ * H_;
    const int write_final =
        ((long long)out_size >= states_elems + (long long)L_ * B_ * H_) ? 1 : 0;

    cudaFuncSetAttribute(gemm_step, cudaFuncAttributeMaxDynamicSharedMemorySize, SMEM_ALLOC);

    prep_W<<<(int)(3 * WSZ / 4 / 256), 256>>>(w_ih, w_hh);
    prep_A<<<(int)(2 * BH / 4 / 256), 256>>>(h0);
    prep_P<<<dim3(NG / 64, 4), 256>>>(emb, w_ih);

    for (int t = 0; t <= T_; t++) {
        gemm_step<<<dim3(NG / NT, B_ / MT, 3), 256, SMEM_ALLOC>>>(t);
        gate_step<<<dim3(256, 2), 256>>>(out, input, h0, b_ih, b_hh, t, write_final);
    }
}

// round 6
// speedup vs baseline: 1.0074x; 1.0074x over previous
#include <cuda_runtime.h>
#include <cuda_bf16.h>
#include <cstdint>

// GRU encoder B=512 T=128 E=H=512 L=2 — HMMA bf16 hi/lo 3-pass pipeline.
// R6: 3-stage cp.async pipeline (prefetch distance 2 iters) on the R4 tiling
// (CTA 128x128, 8 warps, warp tile 32x64) to remove the per-iteration
// wait_group stall that capped tensor utilization at ~27%.

namespace {

constexpr int B_ = 512, T_ = 128, H_ = 512, L_ = 2;
constexpr int NG = 1536;                  // 3*H
constexpr size_t BH  = (size_t)B_ * H_;
constexpr size_t BNG = (size_t)B_ * NG;
constexpr size_t WSZ = (size_t)NG * 512;  // one weight matrix
constexpr int MT = 128, NT = 128, KC = 64;
constexpr int NITER = 512 / KC;           // 8
constexpr int STAGES = 3;

// stage layout: Ahi | Alo | Bhi | Blo  (rows of 64 bf16 = 128B, SW128)
constexpr int AH_OFF = 0;
constexpr int AL_OFF = MT * 128;               // 16384
constexpr int BH_OFF = 2 * MT * 128;           // 32768
constexpr int BL_OFF = BH_OFF + NT * 128;      // 49152
constexpr int STAGE_BYTES = BL_OFF + NT * 128; // 65536
constexpr int SMEM_ALLOC = STAGES * STAGE_BYTES; // 196608 -> 1 CTA/SM

__device__ __align__(256) float g_scr[3 * BNG];          // gh0 | gi1 | gh1
__device__ __align__(256) float g_P[128 * NG];           // emb @ Wi0^T (exact fp32)
__device__ __align__(256) __nv_bfloat16 g_Whi[3 * WSZ];  // Wh0 | Wi1 | Wh1 (hi)
__device__ __align__(256) __nv_bfloat16 g_Wlo[3 * WSZ];
__device__ __align__(256) __nv_bfloat16 g_Ahi[2 * BH];   // per-layer hidden (hi)
__device__ __align__(256) __nv_bfloat16 g_Alo[2 * BH];

__device__ __forceinline__ uint32_t s2u(const void* p) {
    uint32_t a;
    asm("{ .reg .u64 t; cvta.to.shared.u64 t, %1; cvt.u32.u64 %0, t; }" : "=r"(a) : "l"(p));
    return a;
}
__device__ __forceinline__ uint32_t sw128(uint32_t b) { return b ^ ((b >> 3) & 0x70); }
__device__ __forceinline__ void cp16(uint32_t dst, const void* src) {
    asm volatile("cp.async.cg.shared.global [%0], [%1], 16;" :: "r"(dst), "l"(src));
}
__device__ __forceinline__ void ldsm4(uint32_t* r, uint32_t addr) {
    asm volatile("ldmatrix.sync.aligned.m8n8.x4.shared.b16 {%0,%1,%2,%3}, [%4];"
                 : "=r"(r[0]), "=r"(r[1]), "=r"(r[2]), "=r"(r[3]) : "r"(addr));
}
__device__ __forceinline__ void mma16816(float* c, const uint32_t* a, const uint32_t* b) {
    asm volatile(
        "mma.sync.aligned.m16n8k16.row.col.f32.bf16.bf16.f32 "
        "{%0,%1,%2,%3}, {%4,%5,%6,%7}, {%8,%9}, {%0,%1,%2,%3};"
        : "+f"(c[0]), "+f"(c[1]), "+f"(c[2]), "+f"(c[3])
        : "r"(a[0]), "r"(a[1]), "r"(a[2]), "r"(a[3]), "r"(b[0]), "r"(b[1]));
}

// ============================ GEMM ============================
// job0: gh0 = h0(t-1) @ Wh0^T | job1: gi1 = h0(t-1) @ Wi1^T | job2: gh1 = h1(t-2) @ Wh1^T
__global__ void __launch_bounds__(256, 1) gemm_step(int t) {
    const int job = blockIdx.z;
    if (job == 0) { if (t >= T_) return; } else { if (t < 1) return; }

    const int a_sel = (job == 2) ? 1 : 0;
    const __nv_bfloat16* __restrict__ Ahi = g_Ahi + (size_t)a_sel * BH;
    const __nv_bfloat16* __restrict__ Alo = g_Alo + (size_t)a_sel * BH;
    const __nv_bfloat16* __restrict__ Bhi = g_Whi + (size_t)job * WSZ;
    const __nv_bfloat16* __restrict__ Blo = g_Wlo + (size_t)job * WSZ;
    float* __restrict__ dst = g_scr + (size_t)job * BNG;

    const int m0 = blockIdx.y * MT, n0 = blockIdx.x * NT;
    const int tid = threadIdx.x, wid = tid >> 5, lane = tid & 31;
    const int warp_m = wid & 3, warp_n = wid >> 2;    // 4M x 2N, warp tile 32x64

    extern __shared__ char smraw[];
    const uint32_t smb = s2u(smraw);

    auto load_stage = [&](int buf, int k0) {
        const uint32_t st = smb + buf * STAGE_BYTES;
        #pragma unroll
        for (int i = 0; i < 4; i++) {
            int c = tid + i * 256;            // 0..1023 chunks per tile
            int row = c >> 3, col = c & 7;
            uint32_t off = sw128((uint32_t)(row * 128 + col * 16));
            size_t ga = (size_t)(m0 + row) * 512 + k0 + col * 8;
            size_t gb = (size_t)(n0 + row) * 512 + k0 + col * 8;
            cp16(st + AH_OFF + off, Ahi + ga);
            cp16(st + AL_OFF + off, Alo + ga);
            cp16(st + BH_OFF + off, Bhi + gb);
            cp16(st + BL_OFF + off, Blo + gb);
        }
        asm volatile("cp.async.commit_group;");
    };

    // prologue: 3 stages in flight
    load_stage(0, 0);
    load_stage(1, KC);
    load_stage(2, 2 * KC);

    // ldmatrix lane selectors
    const int aRow  = warp_m * 32 + (lane & 15);
    const int aKsel = ((lane >> 4) & 1) * 16;                    // bytes
    const int bRow  = warp_n * 64 + ((lane >> 4) & 1) * 8 + (lane & 7);
    const int bKsel = ((lane >> 3) & 1) * 16;                    // bytes

    float acc[2][8][4];
    #pragma unroll
    for (int mi = 0; mi < 2; mi++)
        #pragma unroll
        for (int ni = 0; ni < 8; ni++)
            #pragma unroll
            for (int q = 0; q < 4; q++) acc[mi][ni][q] = 0.0f;

    for (int j = 0; j < NITER; j++) {
        asm volatile("cp.async.wait_group 2;");   // stage j landed (2 newer in flight)
        __syncthreads();
        const uint32_t st = smb + (j % STAGES) * STAGE_BYTES;

        #pragma unroll
        for (int ks = 0; ks < KC / 16; ks++) {
            uint32_t ah[2][4], al[2][4], bh[4][4], bl[4][4];
            #pragma unroll
            for (int mi = 0; mi < 2; mi++) {
                uint32_t off = sw128((uint32_t)((aRow + mi * 16) * 128 + ks * 32 + aKsel));
                ldsm4(ah[mi], st + AH_OFF + off);
                ldsm4(al[mi], st + AL_OFF + off);
            }
            #pragma unroll
            for (int g = 0; g < 4; g++) {
                uint32_t off = sw128((uint32_t)((bRow + g * 16) * 128 + ks * 32 + bKsel));
                ldsm4(bh[g], st + BH_OFF + off);
                ldsm4(bl[g], st + BL_OFF + off);
            }
            #pragma unroll
            for (int mi = 0; mi < 2; mi++)
                #pragma unroll
                for (int ni = 0; ni < 8; ni++) {
                    const uint32_t* bhp = &bh[ni >> 1][(ni & 1) * 2];
                    const uint32_t* blp = &bl[ni >> 1][(ni & 1) * 2];
                    mma16816(acc[mi][ni], ah[mi], bhp);
                    mma16816(acc[mi][ni], ah[mi], blp);
                    mma16816(acc[mi][ni], al[mi], bhp);
                }
        }
        // all warps done with buffer j%3 -> refill it for stage j+3
        __syncthreads();
        if (j + STAGES < NITER) load_stage(j % STAGES, (j + STAGES) * KC);
        else asm volatile("cp.async.commit_group;");   // empty group, uniform counting
    }

    // epilogue: fragment scatter to fp32 scratch
    #pragma unroll
    for (int mi = 0; mi < 2; mi++) {
        int row = m0 + warp_m * 32 + mi * 16 + (lane >> 2);
        #pragma unroll
        for (int ni = 0; ni < 8; ni++) {
            int col = n0 + warp_n * 64 + ni * 8 + (lane & 3) * 2;
            *(float2*)(dst + (size_t)row * NG + col) =
                make_float2(acc[mi][ni][0], acc[mi][ni][1]);
            *(float2*)(dst + (size_t)(row + 8) * NG + col) =
                make_float2(acc[mi][ni][2], acc[mi][ni][3]);
        }
    }
}

// ============================ gates ============================
__global__ void __launch_bounds__(256) gate_step(
        float* __restrict__ out, const int* __restrict__ input,
        const float* __restrict__ h0init,
        const float* __restrict__ b_ih, const float* __restrict__ b_hh,
        int t, int write_final) {
    const int layer = blockIdx.y;
    const int s = (layer == 0) ? t : t - 1;
    if (s < 0 || s >= T_) return;

    const int e4 = blockIdx.x * 256 + threadIdx.x;   // 65536 float4 per layer
    const int b = e4 >> 7;
    const int h = (e4 & 127) * 4;

    float4 gi_r, gi_z, gi_n;
    if (layer == 0) {
        const float* P = g_P + (size_t)input[b * T_ + s] * NG;
        gi_r = *(const float4*)(P + h);
        gi_z = *(const float4*)(P + 512 + h);
        gi_n = *(const float4*)(P + 1024 + h);
    } else {
        const float* G = g_scr + BNG + (size_t)b * NG;   // gi1
        gi_r = *(const float4*)(G + h);
        gi_z = *(const float4*)(G + 512 + h);
        gi_n = *(const float4*)(G + 1024 + h);
    }
    const float* GH = g_scr + (layer == 0 ? (size_t)0 : 2 * BNG) + (size_t)b * NG;
    float4 gh_r = *(const float4*)(GH + h);
    float4 gh_z = *(const float4*)(GH + 512 + h);
    float4 gh_n = *(const float4*)(GH + 1024 + h);

    const float* hp_ptr = (s == 0) ? (h0init + (size_t)layer * BH)
                                   : (out + (size_t)((s - 1) * L_ + layer) * BH);
    float4 hp = *(const float4*)(hp_ptr + (size_t)b * H_ + h);

    const float* bi = b_ih + layer * NG;
    const float* bh = b_hh + layer * NG;
    float4 bir = *(const float4*)(bi + h), biz = *(const float4*)(bi + 512 + h),
           bin = *(const float4*)(bi + 1024 + h);
    float4 bhr = *(const float4*)(bh + h), bhz = *(const float4*)(bh + 512 + h),
           bhn = *(const float4*)(bh + 1024 + h);

    float hv[4];
    #pragma unroll
    for (int i = 0; i < 4; i++) {
        float r = 1.0f / (1.0f + expf(-((&gi_r.x)[i] + (&bir.x)[i] + (&gh_r.x)[i] + (&bhr.x)[i])));
        float z = 1.0f / (1.0f + expf(-((&gi_z.x)[i] + (&biz.x)[i] + (&gh_z.x)[i] + (&bhz.x)[i])));
        float n = tanhf((&gi_n.x)[i] + (&bin.x)[i] + r * ((&gh_n.x)[i] + (&bhn.x)[i]));
        hv[i] = (1.0f - z) * n + z * (&hp.x)[i];
    }

    const size_t eoff = (size_t)b * H_ + h;
    *(float4*)(out + (size_t)(s * L_ + layer) * BH + eoff) =
        make_float4(hv[0], hv[1], hv[2], hv[3]);

    __nv_bfloat16* ah = g_Ahi + (size_t)layer * BH + eoff;
    __nv_bfloat16* al = g_Alo + (size_t)layer * BH + eoff;
    #pragma unroll
    for (int i = 0; i < 4; i++) {
        __nv_bfloat16 hi = __float2bfloat16(hv[i]);
        ah[i] = hi;
        al[i] = __float2bfloat16(hv[i] - __bfloat162float(hi));
    }

    if (write_final && s == T_ - 1)
        *(float4*)(out + (size_t)T_ * L_ * BH + (size_t)layer * BH + eoff) =
            make_float4(hv[0], hv[1], hv[2], hv[3]);
}

// ============================ prep ============================
__global__ void __launch_bounds__(256) prep_P(const float* __restrict__ emb,
                                              const float* __restrict__ w_ih) {
    // grid (NG/64, 128/32): P[v][n] = sum_k emb[v][k] * Wi0[n][k]  (exact fp32)
    const int n = blockIdx.x * 64 + (threadIdx.x & 63);
    const int vl = (threadIdx.x >> 6) * 8;
    __shared__ float es[64][33];
    float acc[8] = {};
    for (int k0 = 0; k0 < 512; k0 += 64) {
        __syncthreads();
        #pragma unroll
        for (int i = 0; i < 2; i++) {
            int lin = threadIdx.x + i * 256;
            int vv = lin >> 4, k4 = lin & 15;
            float4 e = *(const float4*)(emb + (size_t)(blockIdx.y * 32 + vv) * 512 + k0 + k4 * 4);
            es[k4 * 4 + 0][vv] = e.x; es[k4 * 4 + 1][vv] = e.y;
            es[k4 * 4 + 2][vv] = e.z; es[k4 * 4 + 3][vv] = e.w;
        }
        __syncthreads();
        const float* wp = w_ih + (size_t)n * 512 + k0;
        #pragma unroll 16
        for (int kk = 0; kk < 64; kk++) {
            float wv = wp[kk];
            #pragma unroll
            for (int j = 0; j < 8; j++) acc[j] = fmaf(wv, es[kk][vl + j], acc[j]);
        }
    }
    for (int j = 0; j < 8; j++)
        g_P[(size_t)(blockIdx.y * 32 + vl + j) * NG + n] = acc[j];
}

__global__ void __launch_bounds__(256) prep_W(const float* __restrict__ w_ih,
                                              const float* __restrict__ w_hh) {
    size_t e4 = ((size_t)blockIdx.x * 256 + threadIdx.x) * 4;   // over 3*WSZ
    size_t job = e4 / WSZ, off = e4 % WSZ;
    const float* src = (job == 0) ? (w_hh + off)
                     : (job == 1) ? (w_ih + WSZ + off) : (w_hh + WSZ + off);
    float4 v = *(const float4*)src;
    union { __nv_bfloat16 b[4]; uint2 u; } hi, lo;
    float f[4] = {v.x, v.y, v.z, v.w};
    #pragma unroll
    for (int i = 0; i < 4; i++) {
        hi.b[i] = __float2bfloat16(f[i]);
        lo.b[i] = __float2bfloat16(f[i] - __bfloat162float(hi.b[i]));
    }
    *(uint2*)(g_Whi + e4) = hi.u;
    *(uint2*)(g_Wlo + e4) = lo.u;
}

__global__ void __launch_bounds__(256) prep_A(const float* __restrict__ h0) {
    size_t e4 = ((size_t)blockIdx.x * 256 + threadIdx.x) * 4;   // over 2*BH
    float4 v = *(const float4*)(h0 + e4);
    union { __nv_bfloat16 b[4]; uint2 u; } hi, lo;
    float f[4] = {v.x, v.y, v.z, v.w};
    #pragma unroll
    for (int i = 0; i < 4; i++) {
        hi.b[i] = __float2bfloat16(f[i]);
        lo.b[i] = __float2bfloat16(f[i] - __bfloat162float(hi.b[i]));
    }
    *(uint2*)(g_Ahi + e4) = hi.u;
    *(uint2*)(g_Alo + e4) = lo.u;
}

} // namespace

extern "C" void kernel_launch(void* const* d_in, const int* in_sizes, int n_in,
                              void* d_out, int out_size) {
    const int*   input = (const int*)  d_in[0];
    const float* h0    = (const float*)d_in[1];
    const float* emb   = (const float*)d_in[2];
    const float* w_ih  = (const float*)d_in[3];
    const float* w_hh  = (const float*)d_in[4];
    const float* b_ih  = (const float*)d_in[5];
    const float* b_hh  = (const float*)d_in[6];
    float* out = (float*)d_out;

    const long long states_elems = (long long)T_ * L_ * B_ * H_;
    const int write_final =
        ((long long)out_size >= states_elems + (long long)L_ * B_ * H_) ? 1 : 0;

    cudaFuncSetAttribute(gemm_step, cudaFuncAttributeMaxDynamicSharedMemorySize, SMEM_ALLOC);

    prep_W<<<(int)(3 * WSZ / 4 / 256), 256>>>(w_ih, w_hh);
    prep_A<<<(int)(2 * BH / 4 / 256), 256>>>(h0);
    prep_P<<<dim3(NG / 64, 4), 256>>>(emb, w_ih);

    for (int t = 0; t <= T_; t++) {
        gemm_step<<<dim3(NG / NT, B_ / MT, 3), 256, SMEM_ALLOC>>>(t);
        gate_step<<<dim3(256, 2), 256>>>(out, input, h0, b_ih, b_hh, t, write_final);
    }
}

// round 7
// speedup vs baseline: 1.2692x; 1.2599x over previous
#include <cuda_runtime.h>
#include <cuda_fp16.h>
#include <cuda_bf16.h>
#include <cstdint>

// GRU encoder B=512 T=128 E=H=512 L=2 — HMMA fp16 2-pass pipeline.
// R7: legacy mma.sync throughput is the binder (~12.6cyc/HMMA/SMSP invariant
// across tilings), so reduce MMA count: fp16 weights split hi/lo (exact),
// fp16-rounded activations, 2 passes instead of bf16's 3.
// Weights pre-scaled by 64 so Wlo stays in fp16 normal range; gates unscale.

namespace {

constexpr int B_ = 512, T_ = 128, H_ = 512, L_ = 2;
constexpr int NG = 1536;                  // 3*H
constexpr size_t BH  = (size_t)B_ * H_;
constexpr size_t BNG = (size_t)B_ * NG;
constexpr size_t WSZ = (size_t)NG * 512;  // one weight matrix
constexpr int MT = 128, NT = 128, KC = 64;
constexpr int NITER = 512 / KC;           // 8
constexpr int STAGES = 3;
constexpr float WSCALE = 64.0f;
constexpr float WINV   = 1.0f / 64.0f;

// stage layout: A | Bhi | Blo  (rows of 64 fp16 = 128B, SW128)
constexpr int A_OFF  = 0;
constexpr int BH_OFF = MT * 128;               // 16384
constexpr int BL_OFF = BH_OFF + NT * 128;      // 32768
constexpr int STAGE_BYTES = BL_OFF + NT * 128; // 49152
constexpr int SMEM_ALLOC = STAGES * STAGE_BYTES; // 147456 -> 1 CTA/SM

__device__ __align__(256) float g_scr[3 * BNG];     // gh0 | gi1 | gh1 (64x scaled)
__device__ __align__(256) float g_P[128 * NG];      // emb @ Wi0^T (exact fp32)
__device__ __align__(256) __half g_Whi[3 * WSZ];    // 64*W hi: Wh0 | Wi1 | Wh1
__device__ __align__(256) __half g_Wlo[3 * WSZ];    // 64*W lo
__device__ __align__(256) __half g_Ah[2 * BH];      // per-layer hidden, fp16

__device__ __forceinline__ uint32_t s2u(const void* p) {
    uint32_t a;
    asm("{ .reg .u64 t; cvta.to.shared.u64 t, %1; cvt.u32.u64 %0, t; }" : "=r"(a) : "l"(p));
    return a;
}
__device__ __forceinline__ uint32_t sw128(uint32_t b) { return b ^ ((b >> 3) & 0x70); }
__device__ __forceinline__ void cp16(uint32_t dst, const void* src) {
    asm volatile("cp.async.cg.shared.global [%0], [%1], 16;" :: "r"(dst), "l"(src));
}
__device__ __forceinline__ void ldsm4(uint32_t* r, uint32_t addr) {
    asm volatile("ldmatrix.sync.aligned.m8n8.x4.shared.b16 {%0,%1,%2,%3}, [%4];"
                 : "=r"(r[0]), "=r"(r[1]), "=r"(r[2]), "=r"(r[3]) : "r"(addr));
}
__device__ __forceinline__ void mma16816(float* c, const uint32_t* a, const uint32_t* b) {
    asm volatile(
        "mma.sync.aligned.m16n8k16.row.col.f32.f16.f16.f32 "
        "{%0,%1,%2,%3}, {%4,%5,%6,%7}, {%8,%9}, {%0,%1,%2,%3};"
        : "+f"(c[0]), "+f"(c[1]), "+f"(c[2]), "+f"(c[3])
        : "r"(a[0]), "r"(a[1]), "r"(a[2]), "r"(a[3]), "r"(b[0]), "r"(b[1]));
}

// ============================ GEMM ============================
// job0: gh0 = h0(t-1) @ Wh0^T | job1: gi1 = h0(t-1) @ Wi1^T | job2: gh1 = h1(t-2) @ Wh1^T
__global__ void __launch_bounds__(256, 1) gemm_step(int t) {
    const int job = blockIdx.z;
    if (job == 0) { if (t >= T_) return; } else { if (t < 1) return; }

    const int a_sel = (job == 2) ? 1 : 0;
    const __half* __restrict__ Asrc = g_Ah + (size_t)a_sel * BH;
    const __half* __restrict__ Bhi  = g_Whi + (size_t)job * WSZ;
    const __half* __restrict__ Blo  = g_Wlo + (size_t)job * WSZ;
    float* __restrict__ dst = g_scr + (size_t)job * BNG;

    const int m0 = blockIdx.y * MT, n0 = blockIdx.x * NT;
    const int tid = threadIdx.x, wid = tid >> 5, lane = tid & 31;
    const int warp_m = wid & 3, warp_n = wid >> 2;    // 4M x 2N, warp tile 32x64

    extern __shared__ char smraw[];
    const uint32_t smb = s2u(smraw);

    auto load_stage = [&](int buf, int k0) {
        const uint32_t st = smb + buf * STAGE_BYTES;
        #pragma unroll
        for (int i = 0; i < 4; i++) {
            int c = tid + i * 256;            // 0..1023 chunks per tile
            int row = c >> 3, col = c & 7;
            uint32_t off = sw128((uint32_t)(row * 128 + col * 16));
            size_t ga = (size_t)(m0 + row) * 512 + k0 + col * 8;
            size_t gb = (size_t)(n0 + row) * 512 + k0 + col * 8;
            cp16(st + A_OFF  + off, Asrc + ga);
            cp16(st + BH_OFF + off, Bhi + gb);
            cp16(st + BL_OFF + off, Blo + gb);
        }
        asm volatile("cp.async.commit_group;");
    };

    load_stage(0, 0);
    load_stage(1, KC);
    load_stage(2, 2 * KC);

    const int aRow  = warp_m * 32 + (lane & 15);
    const int aKsel = ((lane >> 4) & 1) * 16;                    // bytes
    const int bRow  = warp_n * 64 + ((lane >> 4) & 1) * 8 + (lane & 7);
    const int bKsel = ((lane >> 3) & 1) * 16;                    // bytes

    float acc[2][8][4];
    #pragma unroll
    for (int mi = 0; mi < 2; mi++)
        #pragma unroll
        for (int ni = 0; ni < 8; ni++)
            #pragma unroll
            for (int q = 0; q < 4; q++) acc[mi][ni][q] = 0.0f;

    for (int j = 0; j < NITER; j++) {
        asm volatile("cp.async.wait_group 2;");
        __syncthreads();
        const uint32_t st = smb + (j % STAGES) * STAGE_BYTES;

        #pragma unroll
        for (int ks = 0; ks < KC / 16; ks++) {
            uint32_t a[2][4], bh[4][4], bl[4][4];
            #pragma unroll
            for (int mi = 0; mi < 2; mi++) {
                uint32_t off = sw128((uint32_t)((aRow + mi * 16) * 128 + ks * 32 + aKsel));
                ldsm4(a[mi], st + A_OFF + off);
            }
            #pragma unroll
            for (int g = 0; g < 4; g++) {
                uint32_t off = sw128((uint32_t)((bRow + g * 16) * 128 + ks * 32 + bKsel));
                ldsm4(bh[g], st + BH_OFF + off);
                ldsm4(bl[g], st + BL_OFF + off);
            }
            #pragma unroll
            for (int mi = 0; mi < 2; mi++)
                #pragma unroll
                for (int ni = 0; ni < 8; ni++) {
                    const uint32_t* bhp = &bh[ni >> 1][(ni & 1) * 2];
                    const uint32_t* blp = &bl[ni >> 1][(ni & 1) * 2];
                    mma16816(acc[mi][ni], a[mi], bhp);
                    mma16816(acc[mi][ni], a[mi], blp);
                }
        }
        __syncthreads();
        if (j + STAGES < NITER) load_stage(j % STAGES, (j + STAGES) * KC);
        else asm volatile("cp.async.commit_group;");
    }

    #pragma unroll
    for (int mi = 0; mi < 2; mi++) {
        int row = m0 + warp_m * 32 + mi * 16 + (lane >> 2);
        #pragma unroll
        for (int ni = 0; ni < 8; ni++) {
            int col = n0 + warp_n * 64 + ni * 8 + (lane & 3) * 2;
            *(float2*)(dst + (size_t)row * NG + col) =
                make_float2(acc[mi][ni][0], acc[mi][ni][1]);
            *(float2*)(dst + (size_t)(row + 8) * NG + col) =
                make_float2(acc[mi][ni][2], acc[mi][ni][3]);
        }
    }
}

// ============================ gates ============================
__global__ void __launch_bounds__(256) gate_step(
        float* __restrict__ out, const int* __restrict__ input,
        const float* __restrict__ h0init,
        const float* __restrict__ b_ih, const float* __restrict__ b_hh,
        int t, int write_final) {
    const int layer = blockIdx.y;
    const int s = (layer == 0) ? t : t - 1;
    if (s < 0 || s >= T_) return;

    const int e4 = blockIdx.x * 256 + threadIdx.x;   // 65536 float4 per layer
    const int b = e4 >> 7;
    const int h = (e4 & 127) * 4;

    // gi: layer0 from exact-fp32 P (no scale), layer1 from scratch (64x scaled)
    float gi_sc = (layer == 0) ? 1.0f : WINV;
    float4 gi_r, gi_z, gi_n;
    if (layer == 0) {
        const float* P = g_P + (size_t)input[b * T_ + s] * NG;
        gi_r = *(const float4*)(P + h);
        gi_z = *(const float4*)(P + 512 + h);
        gi_n = *(const float4*)(P + 1024 + h);
    } else {
        const float* G = g_scr + BNG + (size_t)b * NG;   // gi1
        gi_r = *(const float4*)(G + h);
        gi_z = *(const float4*)(G + 512 + h);
        gi_n = *(const float4*)(G + 1024 + h);
    }
    const float* GH = g_scr + (layer == 0 ? (size_t)0 : 2 * BNG) + (size_t)b * NG;
    float4 gh_r = *(const float4*)(GH + h);
    float4 gh_z = *(const float4*)(GH + 512 + h);
    float4 gh_n = *(const float4*)(GH + 1024 + h);

    const float* hp_ptr = (s == 0) ? (h0init + (size_t)layer * BH)
                                   : (out + (size_t)((s - 1) * L_ + layer) * BH);
    float4 hp = *(const float4*)(hp_ptr + (size_t)b * H_ + h);

    const float* bi = b_ih + layer * NG;
    const float* bh = b_hh + layer * NG;
    float4 bir = *(const float4*)(bi + h), biz = *(const float4*)(bi + 512 + h),
           bin = *(const float4*)(bi + 1024 + h);
    float4 bhr = *(const float4*)(bh + h), bhz = *(const float4*)(bh + 512 + h),
           bhn = *(const float4*)(bh + 1024 + h);

    float hv[4];
    #pragma unroll
    for (int i = 0; i < 4; i++) {
        float ir = (&gi_r.x)[i] * gi_sc + (&bir.x)[i];
        float iz = (&gi_z.x)[i] * gi_sc + (&biz.x)[i];
        float in_ = (&gi_n.x)[i] * gi_sc + (&bin.x)[i];
        float hr = (&gh_r.x)[i] * WINV + (&bhr.x)[i];
        float hz = (&gh_z.x)[i] * WINV + (&bhz.x)[i];
        float hn = (&gh_n.x)[i] * WINV + (&bhn.x)[i];
        float r = 1.0f / (1.0f + expf(-(ir + hr)));
        float z = 1.0f / (1.0f + expf(-(iz + hz)));
        float n = tanhf(in_ + r * hn);
        hv[i] = (1.0f - z) * n + z * (&hp.x)[i];
    }

    const size_t eoff = (size_t)b * H_ + h;
    *(float4*)(out + (size_t)(s * L_ + layer) * BH + eoff) =
        make_float4(hv[0], hv[1], hv[2], hv[3]);

    __half* ah = g_Ah + (size_t)layer * BH + eoff;
    #pragma unroll
    for (int i = 0; i < 4; i++) ah[i] = __float2half_rn(hv[i]);

    if (write_final && s == T_ - 1)
        *(float4*)(out + (size_t)T_ * L_ * BH + (size_t)layer * BH + eoff) =
            make_float4(hv[0], hv[1], hv[2], hv[3]);
}

// ============================ prep ============================
__global__ void __launch_bounds__(256) prep_P(const float* __restrict__ emb,
                                              const float* __restrict__ w_ih) {
    // grid (NG/64, 128/32): P[v][n] = sum_k emb[v][k] * Wi0[n][k]  (exact fp32)
    const int n = blockIdx.x * 64 + (threadIdx.x & 63);
    const int vl = (threadIdx.x >> 6) * 8;
    __shared__ float es[64][33];
    float acc[8] = {};
    for (int k0 = 0; k0 < 512; k0 += 64) {
        __syncthreads();
        #pragma unroll
        for (int i = 0; i < 2; i++) {
            int lin = threadIdx.x + i * 256;
            int vv = lin >> 4, k4 = lin & 15;
            float4 e = *(const float4*)(emb + (size_t)(blockIdx.y * 32 + vv) * 512 + k0 + k4 * 4);
            es[k4 * 4 + 0][vv] = e.x; es[k4 * 4 + 1][vv] = e.y;
            es[k4 * 4 + 2][vv] = e.z; es[k4 * 4 + 3][vv] = e.w;
        }
        __syncthreads();
        const float* wp = w_ih + (size_t)n * 512 + k0;
        #pragma unroll 16
        for (int kk = 0; kk < 64; kk++) {
            float wv = wp[kk];
            #pragma unroll
            for (int j = 0; j < 8; j++) acc[j] = fmaf(wv, es[kk][vl + j], acc[j]);
        }
    }
    for (int j = 0; j < 8; j++)
        g_P[(size_t)(blockIdx.y * 32 + vl + j) * NG + n] = acc[j];
}

__global__ void __launch_bounds__(256) prep_W(const float* __restrict__ w_ih,
                                              const float* __restrict__ w_hh) {
    size_t e4 = ((size_t)blockIdx.x * 256 + threadIdx.x) * 4;   // over 3*WSZ
    size_t job = e4 / WSZ, off = e4 % WSZ;
    const float* src = (job == 0) ? (w_hh + off)
                     : (job == 1) ? (w_ih + WSZ + off) : (w_hh + WSZ + off);
    float4 v = *(const float4*)src;
    union { __half b[4]; uint2 u; } hi, lo;
    float f[4] = {v.x * WSCALE, v.y * WSCALE, v.z * WSCALE, v.w * WSCALE};
    #pragma unroll
    for (int i = 0; i < 4; i++) {
        hi.b[i] = __float2half_rn(f[i]);
        lo.b[i] = __float2half_rn(f[i] - __half2float(hi.b[i]));
    }
    *(uint2*)(g_Whi + e4) = hi.u;
    *(uint2*)(g_Wlo + e4) = lo.u;
}

__global__ void __launch_bounds__(256) prep_A(const float* __restrict__ h0) {
    size_t e4 = ((size_t)blockIdx.x * 256 + threadIdx.x) * 4;   // over 2*BH
    float4 v = *(const float4*)(h0 + e4);
    union { __half b[4]; uint2 u; } hh;
    hh.b[0] = __float2half_rn(v.x); hh.b[1] = __float2half_rn(v.y);
    hh.b[2] = __float2half_rn(v.z); hh.b[3] = __float2half_rn(v.w);
    *(uint2*)(g_Ah + e4) = hh.u;
}

} // namespace

extern "C" void kernel_launch(void* const* d_in, const int* in_sizes, int n_in,
                              void* d_out, int out_size) {
    const int*   input = (const int*)  d_in[0];
    const float* h0    = (const float*)d_in[1];
    const float* emb   = (const float*)d_in[2];
    const float* w_ih  = (const float*)d_in[3];
    const float* w_hh  = (const float*)d_in[4];
    const float* b_ih  = (const float*)d_in[5];
    const float* b_hh  = (const float*)d_in[6];
    float* out = (float*)d_out;

    const long long states_elems = (long long)T_ * L_ * B_ * H_;
    const int write_final =
        ((long long)out_size >= states_elems + (long long)L_ * B_ * H_) ? 1 : 0;

    cudaFuncSetAttribute(gemm_step, cudaFuncAttributeMaxDynamicSharedMemorySize, SMEM_ALLOC);

    prep_W<<<(int)(3 * WSZ / 4 / 256), 256>>>(w_ih, w_hh);
    prep_A<<<(int)(2 * BH / 4 / 256), 256>>>(h0);
    prep_P<<<dim3(NG / 64, 4), 256>>>(emb, w_ih);

    for (int t = 0; t <= T_; t++) {
        gemm_step<<<dim3(NG / NT, B_ / MT, 3), 256, SMEM_ALLOC>>>(t);
        gate_step<<<dim3(256, 2), 256>>>(out, input, h0, b_ih, b_hh, t, write_final);
    }
}

// round 8
// speedup vs baseline: 1.6311x; 1.2851x over previous
#include <cuda_runtime.h>
#include <cuda_fp16.h>
#include <cstdint>

// GRU encoder B=512 T=128 E=H=512 L=2 — HMMA fp16 1-pass pipeline.
// R8: duration scales with MMA count (measured: gemm ≈ 3.5µs fixed + 4.6µs/pass),
// and R7's rel_err 5.8e-5 leaves 17x margin — so drop the Wlo correction pass.
// Single fp16 weights + fp16 activations, fp32 accum. Predicted rel_err ~1e-4.

namespace {

constexpr int B_ = 512, T_ = 128, H_ = 512, L_ = 2;
constexpr int NG = 1536;                  // 3*H
constexpr size_t BH  = (size_t)B_ * H_;
constexpr size_t BNG = (size_t)B_ * NG;
constexpr size_t WSZ = (size_t)NG * 512;  // one weight matrix
constexpr int MT = 128, NT = 128, KC = 64;
constexpr int NITER = 512 / KC;           // 8
constexpr int STAGES = 3;

// stage layout: A | B  (rows of 64 fp16 = 128B, SW128)
constexpr int A_OFF  = 0;
constexpr int B_OFF  = MT * 128;               // 16384
constexpr int STAGE_BYTES = B_OFF + NT * 128;  // 32768
constexpr int SMEM_ALLOC = STAGES * STAGE_BYTES; // 98304

__device__ __align__(256) float g_scr[3 * BNG];     // gh0 | gi1 | gh1
__device__ __align__(256) float g_P[128 * NG];      // emb @ Wi0^T (exact fp32)
__device__ __align__(256) __half g_W[3 * WSZ];      // fp16 W: Wh0 | Wi1 | Wh1
__device__ __align__(256) __half g_Ah[2 * BH];      // per-layer hidden, fp16

__device__ __forceinline__ uint32_t s2u(const void* p) {
    uint32_t a;
    asm("{ .reg .u64 t; cvta.to.shared.u64 t, %1; cvt.u32.u64 %0, t; }" : "=r"(a) : "l"(p));
    return a;
}
__device__ __forceinline__ uint32_t sw128(uint32_t b) { return b ^ ((b >> 3) & 0x70); }
__device__ __forceinline__ void cp16(uint32_t dst, const void* src) {
    asm volatile("cp.async.cg.shared.global [%0], [%1], 16;" :: "r"(dst), "l"(src));
}
__device__ __forceinline__ void ldsm4(uint32_t* r, uint32_t addr) {
    asm volatile("ldmatrix.sync.aligned.m8n8.x4.shared.b16 {%0,%1,%2,%3}, [%4];"
                 : "=r"(r[0]), "=r"(r[1]), "=r"(r[2]), "=r"(r[3]) : "r"(addr));
}
__device__ __forceinline__ void mma16816(float* c, const uint32_t* a, const uint32_t* b) {
    asm volatile(
        "mma.sync.aligned.m16n8k16.row.col.f32.f16.f16.f32 "
        "{%0,%1,%2,%3}, {%4,%5,%6,%7}, {%8,%9}, {%0,%1,%2,%3};"
        : "+f"(c[0]), "+f"(c[1]), "+f"(c[2]), "+f"(c[3])
        : "r"(a[0]), "r"(a[1]), "r"(a[2]), "r"(a[3]), "r"(b[0]), "r"(b[1]));
}

// ============================ GEMM ============================
// job0: gh0 = h0(t-1) @ Wh0^T | job1: gi1 = h0(t-1) @ Wi1^T | job2: gh1 = h1(t-2) @ Wh1^T
__global__ void __launch_bounds__(256, 1) gemm_step(int t) {
    const int job = blockIdx.z;
    if (job == 0) { if (t >= T_) return; } else { if (t < 1) return; }

    const int a_sel = (job == 2) ? 1 : 0;
    const __half* __restrict__ Asrc = g_Ah + (size_t)a_sel * BH;
    const __half* __restrict__ Bsrc = g_W + (size_t)job * WSZ;
    float* __restrict__ dst = g_scr + (size_t)job * BNG;

    const int m0 = blockIdx.y * MT, n0 = blockIdx.x * NT;
    const int tid = threadIdx.x, wid = tid >> 5, lane = tid & 31;
    const int warp_m = wid & 3, warp_n = wid >> 2;    // 4M x 2N, warp tile 32x64

    extern __shared__ char smraw[];
    const uint32_t smb = s2u(smraw);

    auto load_stage = [&](int buf, int k0) {
        const uint32_t st = smb + buf * STAGE_BYTES;
        #pragma unroll
        for (int i = 0; i < 4; i++) {
            int c = tid + i * 256;            // 0..1023 chunks per tile
            int row = c >> 3, col = c & 7;
            uint32_t off = sw128((uint32_t)(row * 128 + col * 16));
            cp16(st + A_OFF + off, Asrc + (size_t)(m0 + row) * 512 + k0 + col * 8);
            cp16(st + B_OFF + off, Bsrc + (size_t)(n0 + row) * 512 + k0 + col * 8);
        }
        asm volatile("cp.async.commit_group;");
    };

    load_stage(0, 0);
    load_stage(1, KC);
    load_stage(2, 2 * KC);

    const int aRow  = warp_m * 32 + (lane & 15);
    const int aKsel = ((lane >> 4) & 1) * 16;                    // bytes
    const int bRow  = warp_n * 64 + ((lane >> 4) & 1) * 8 + (lane & 7);
    const int bKsel = ((lane >> 3) & 1) * 16;                    // bytes

    float acc[2][8][4];
    #pragma unroll
    for (int mi = 0; mi < 2; mi++)
        #pragma unroll
        for (int ni = 0; ni < 8; ni++)
            #pragma unroll
            for (int q = 0; q < 4; q++) acc[mi][ni][q] = 0.0f;

    for (int j = 0; j < NITER; j++) {
        asm volatile("cp.async.wait_group 2;");
        __syncthreads();
        const uint32_t st = smb + (j % STAGES) * STAGE_BYTES;

        #pragma unroll
        for (int ks = 0; ks < KC / 16; ks++) {
            uint32_t a[2][4], b[4][4];
            #pragma unroll
            for (int mi = 0; mi < 2; mi++) {
                uint32_t off = sw128((uint32_t)((aRow + mi * 16) * 128 + ks * 32 + aKsel));
                ldsm4(a[mi], st + A_OFF + off);
            }
            #pragma unroll
            for (int g = 0; g < 4; g++) {
                uint32_t off = sw128((uint32_t)((bRow + g * 16) * 128 + ks * 32 + bKsel));
                ldsm4(b[g], st + B_OFF + off);
            }
            #pragma unroll
            for (int mi = 0; mi < 2; mi++)
                #pragma unroll
                for (int ni = 0; ni < 8; ni++)
                    mma16816(acc[mi][ni], a[mi], &b[ni >> 1][(ni & 1) * 2]);
        }
        __syncthreads();
        if (j + STAGES < NITER) load_stage(j % STAGES, (j + STAGES) * KC);
        else asm volatile("cp.async.commit_group;");
    }

    #pragma unroll
    for (int mi = 0; mi < 2; mi++) {
        int row = m0 + warp_m * 32 + mi * 16 + (lane >> 2);
        #pragma unroll
        for (int ni = 0; ni < 8; ni++) {
            int col = n0 + warp_n * 64 + ni * 8 + (lane & 3) * 2;
            *(float2*)(dst + (size_t)row * NG + col) =
                make_float2(acc[mi][ni][0], acc[mi][ni][1]);
            *(float2*)(dst + (size_t)(row + 8) * NG + col) =
                make_float2(acc[mi][ni][2], acc[mi][ni][3]);
        }
    }
}

// ============================ gates ============================
__global__ void __launch_bounds__(256) gate_step(
        float* __restrict__ out, const int* __restrict__ input,
        const float* __restrict__ h0init,
        const float* __restrict__ b_ih, const float* __restrict__ b_hh,
        int t, int write_final) {
    const int layer = blockIdx.y;
    const int s = (layer == 0) ? t : t - 1;
    if (s < 0 || s >= T_) return;

    const int e4 = blockIdx.x * 256 + threadIdx.x;   // 65536 float4 per layer
    const int b = e4 >> 7;
    const int h = (e4 & 127) * 4;

    float4 gi_r, gi_z, gi_n;
    if (layer == 0) {
        const float* P = g_P + (size_t)input[b * T_ + s] * NG;
        gi_r = *(const float4*)(P + h);
        gi_z = *(const float4*)(P + 512 + h);
        gi_n = *(const float4*)(P + 1024 + h);
    } else {
        const float* G = g_scr + BNG + (size_t)b * NG;   // gi1
        gi_r = *(const float4*)(G + h);
        gi_z = *(const float4*)(G + 512 + h);
        gi_n = *(const float4*)(G + 1024 + h);
    }
    const float* GH = g_scr + (layer == 0 ? (size_t)0 : 2 * BNG) + (size_t)b * NG;
    float4 gh_r = *(const float4*)(GH + h);
    float4 gh_z = *(const float4*)(GH + 512 + h);
    float4 gh_n = *(const float4*)(GH + 1024 + h);

    const float* hp_ptr = (s == 0) ? (h0init + (size_t)layer * BH)
                                   : (out + (size_t)((s - 1) * L_ + layer) * BH);
    float4 hp = *(const float4*)(hp_ptr + (size_t)b * H_ + h);

    const float* bi = b_ih + layer * NG;
    const float* bh = b_hh + layer * NG;
    float4 bir = *(const float4*)(bi + h), biz = *(const float4*)(bi + 512 + h),
           bin = *(const float4*)(bi + 1024 + h);
    float4 bhr = *(const float4*)(bh + h), bhz = *(const float4*)(bh + 512 + h),
           bhn = *(const float4*)(bh + 1024 + h);

    float hv[4];
    #pragma unroll
    for (int i = 0; i < 4; i++) {
        float r = 1.0f / (1.0f + expf(-((&gi_r.x)[i] + (&bir.x)[i] + (&gh_r.x)[i] + (&bhr.x)[i])));
        float z = 1.0f / (1.0f + expf(-((&gi_z.x)[i] + (&biz.x)[i] + (&gh_z.x)[i] + (&bhz.x)[i])));
        float n = tanhf((&gi_n.x)[i] + (&bin.x)[i] + r * ((&gh_n.x)[i] + (&bhn.x)[i]));
        hv[i] = (1.0f - z) * n + z * (&hp.x)[i];
    }

    const size_t eoff = (size_t)b * H_ + h;
    *(float4*)(out + (size_t)(s * L_ + layer) * BH + eoff) =
        make_float4(hv[0], hv[1], hv[2], hv[3]);

    __half* ah = g_Ah + (size_t)layer * BH + eoff;
    #pragma unroll
    for (int i = 0; i < 4; i++) ah[i] = __float2half_rn(hv[i]);

    if (write_final && s == T_ - 1)
        *(float4*)(out + (size_t)T_ * L_ * BH + (size_t)layer * BH + eoff) =
            make_float4(hv[0], hv[1], hv[2], hv[3]);
}

// ============================ prep ============================
__global__ void __launch_bounds__(256) prep_P(const float* __restrict__ emb,
                                              const float* __restrict__ w_ih) {
    // grid (NG/64, 128/32): P[v][n] = sum_k emb[v][k] * Wi0[n][k]  (exact fp32)
    const int n = blockIdx.x * 64 + (threadIdx.x & 63);
    const int vl = (threadIdx.x >> 6) * 8;
    __shared__ float es[64][33];
    float acc[8] = {};
    for (int k0 = 0; k0 < 512; k0 += 64) {
        __syncthreads();
        #pragma unroll
        for (int i = 0; i < 2; i++) {
            int lin = threadIdx.x + i * 256;
            int vv = lin >> 4, k4 = lin & 15;
            float4 e = *(const float4*)(emb + (size_t)(blockIdx.y * 32 + vv) * 512 + k0 + k4 * 4);
            es[k4 * 4 + 0][vv] = e.x; es[k4 * 4 + 1][vv] = e.y;
            es[k4 * 4 + 2][vv] = e.z; es[k4 * 4 + 3][vv] = e.w;
        }
        __syncthreads();
        const float* wp = w_ih + (size_t)n * 512 + k0;
        #pragma unroll 16
        for (int kk = 0; kk < 64; kk++) {
            float wv = wp[kk];
            #pragma unroll
            for (int j = 0; j < 8; j++) acc[j] = fmaf(wv, es[kk][vl + j], acc[j]);
        }
    }
    for (int j = 0; j < 8; j++)
        g_P[(size_t)(blockIdx.y * 32 + vl + j) * NG + n] = acc[j];
}

__global__ void __launch_bounds__(256) prep_W(const float* __restrict__ w_ih,
                                              const float* __restrict__ w_hh) {
    size_t e4 = ((size_t)blockIdx.x * 256 + threadIdx.x) * 4;   // over 3*WSZ
    size_t job = e4 / WSZ, off = e4 % WSZ;
    const float* src = (job == 0) ? (w_hh + off)
                     : (job == 1) ? (w_ih + WSZ + off) : (w_hh + WSZ + off);
    float4 v = *(const float4*)src;
    union { __half b[4]; uint2 u; } hh;
    hh.b[0] = __float2half_rn(v.x); hh.b[1] = __float2half_rn(v.y);
    hh.b[2] = __float2half_rn(v.z); hh.b[3] = __float2half_rn(v.w);
    *(uint2*)(g_W + e4) = hh.u;
}

__global__ void __launch_bounds__(256) prep_A(const float* __restrict__ h0) {
    size_t e4 = ((size_t)blockIdx.x * 256 + threadIdx.x) * 4;   // over 2*BH
    float4 v = *(const float4*)(h0 + e4);
    union { __half b[4]; uint2 u; } hh;
    hh.b[0] = __float2half_rn(v.x); hh.b[1] = __float2half_rn(v.y);
    hh.b[2] = __float2half_rn(v.z); hh.b[3] = __float2half_rn(v.w);
    *(uint2*)(g_Ah + e4) = hh.u;
}

} // namespace

extern "C" void kernel_launch(void* const* d_in, const int* in_sizes, int n_in,
                              void* d_out, int out_size) {
    const int*   input = (const int*)  d_in[0];
    const float* h0    = (const float*)d_in[1];
    const float* emb   = (const float*)d_in[2];
    const float* w_ih  = (const float*)d_in[3];
    const float* w_hh  = (const float*)d_in[4];
    const float* b_ih  = (const float*)d_in[5];
    const float* b_hh  = (const float*)d_in[6];
    float* out = (float*)d_out;

    const long long states_elems = (long long)T_ * L_ * B_ * H_;
    const int write_final =
        ((long long)out_size >= states_elems + (long long)L_ * B_ * H_) ? 1 : 0;

    cudaFuncSetAttribute(gemm_step, cudaFuncAttributeMaxDynamicSharedMemorySize, SMEM_ALLOC);

    prep_W<<<(int)(3 * WSZ / 4 / 256), 256>>>(w_ih, w_hh);
    prep_A<<<(int)(2 * BH / 4 / 256), 256>>>(h0);
    prep_P<<<dim3(NG / 64, 4), 256>>>(emb, w_ih);

    for (int t = 0; t <= T_; t++) {
        gemm_step<<<dim3(NG / NT, B_ / MT, 3), 256, SMEM_ALLOC>>>(t);
        gate_step<<<dim3(256, 2), 256>>>(out, input, h0, b_ih, b_hh, t, write_final);
    }
}